// round 16
// baseline (speedup 1.0000x reference)
#include <cuda_runtime.h>
#include <cuda_bf16.h>
#include <math.h>

#define BT    256
#define NCOLS 5000
#define NVEC  1250      // NCOLS/4
#define NVPAD 1280      // ceil to multiple of BT (uniform warp trips for ballot)
#define TOPK  10
#define MAXB  8192
#define CAP   128

__device__ float        g_row[MAXB];
__device__ unsigned int g_ctr = 0;

// Order-preserving float<->uint bijection: f1<f2  <=>  ordf(f1)<ordf(f2)
__device__ __forceinline__ unsigned int ordf(float f) {
    unsigned int u = __float_as_uint(f);
    return (u & 0x80000000u) ? ~u : (u | 0x80000000u);
}
__device__ __forceinline__ float iordf(unsigned int o) {
    unsigned int u = (o & 0x80000000u) ? (o & 0x7fffffffu) : ~o;
    return __uint_as_float(u);
}

// Combined block reduce: sum(int), max(float), max(float)
__device__ __forceinline__ void blockReduceNMM(int& nv, float& my, float& mu,
                                               int* sci, float* scf) {
    int lane = threadIdx.x & 31, w = threadIdx.x >> 5;
    int n = nv; float a = my, b = mu;
#pragma unroll
    for (int o = 16; o; o >>= 1) {
        n += __shfl_down_sync(0xffffffffu, n, o);
        a = fmaxf(a, __shfl_down_sync(0xffffffffu, a, o));
        b = fmaxf(b, __shfl_down_sync(0xffffffffu, b, o));
    }
    if (lane == 0) { sci[w] = n; scf[w] = a; scf[8 + w] = b; }
    __syncthreads();
    if (w == 0) {
        int nn = lane < 8 ? sci[lane] : 0;
        float aa = lane < 8 ? scf[lane] : -INFINITY;
        float bb = lane < 8 ? scf[8 + lane] : -INFINITY;
#pragma unroll
        for (int o = 4; o; o >>= 1) {
            nn += __shfl_down_sync(0xffffffffu, nn, o);
            aa = fmaxf(aa, __shfl_down_sync(0xffffffffu, aa, o));
            bb = fmaxf(bb, __shfl_down_sync(0xffffffffu, bb, o));
        }
        if (lane == 0) { sci[0] = nn; scf[0] = aa; scf[8] = bb; }
    }
    __syncthreads();
    nv = sci[0]; my = scf[0]; mu = scf[8];
    __syncthreads();
}

// Combined block reduce: three float sums
__device__ __forceinline__ void blockReduce3F(float& a, float& b, float& c, float* scf) {
    int lane = threadIdx.x & 31, w = threadIdx.x >> 5;
#pragma unroll
    for (int o = 16; o; o >>= 1) {
        a += __shfl_down_sync(0xffffffffu, a, o);
        b += __shfl_down_sync(0xffffffffu, b, o);
        c += __shfl_down_sync(0xffffffffu, c, o);
    }
    if (lane == 0) { scf[w] = a; scf[8 + w] = b; scf[16 + w] = c; }
    __syncthreads();
    if (w == 0) {
        float x = lane < 8 ? scf[lane] : 0.0f;
        float y = lane < 8 ? scf[8 + lane] : 0.0f;
        float z = lane < 8 ? scf[16 + lane] : 0.0f;
#pragma unroll
        for (int o = 4; o; o >>= 1) {
            x += __shfl_down_sync(0xffffffffu, x, o);
            y += __shfl_down_sync(0xffffffffu, y, o);
            z += __shfl_down_sync(0xffffffffu, z, o);
        }
        if (lane == 0) { scf[0] = x; scf[8] = y; scf[16] = z; }
    }
    __syncthreads();
    a = scf[0]; b = scf[8]; c = scf[16];
    __syncthreads();
}

// In-place inclusive prefix scan of a 256-int shared array (BT==256 threads).
__device__ __forceinline__ void scan256(int* h, int* wtot) {
    int tid = threadIdx.x, lane = tid & 31, w = tid >> 5;
    int v = h[tid];
#pragma unroll
    for (int o = 1; o < 32; o <<= 1) {
        int t = __shfl_up_sync(0xffffffffu, v, o);
        if (lane >= o) v += t;
    }
    if (lane == 31) wtot[w] = v;
    __syncthreads();
    if (w == 0 && lane < 8) {
        int x = wtot[lane];
#pragma unroll
        for (int o = 1; o < 8; o <<= 1) {
            int t = __shfl_up_sync(0xffu, x, o);
            if (lane >= o) x += t;
        }
        wtot[lane] = x;
    }
    __syncthreads();
    h[tid] = v + (w ? wtot[w - 1] : 0);
    __syncthreads();
}

// Dual scan: two 256-int arrays at once (halves barrier count).
__device__ __forceinline__ void scan256dual(int* ha, int* hb, int* wta, int* wtb) {
    int tid = threadIdx.x, lane = tid & 31, w = tid >> 5;
    int va = ha[tid], vb = hb[tid];
#pragma unroll
    for (int o = 1; o < 32; o <<= 1) {
        int ta = __shfl_up_sync(0xffffffffu, va, o);
        int tb = __shfl_up_sync(0xffffffffu, vb, o);
        if (lane >= o) { va += ta; vb += tb; }
    }
    if (lane == 31) { wta[w] = va; wtb[w] = vb; }
    __syncthreads();
    if (w == 0 && lane < 8) {
        int xa = wta[lane], xb = wtb[lane];
#pragma unroll
        for (int o = 1; o < 8; o <<= 1) {
            int ta = __shfl_up_sync(0xffu, xa, o);
            int tb = __shfl_up_sync(0xffu, xb, o);
            if (lane >= o) { xa += ta; xb += tb; }
        }
        wta[lane] = xa; wtb[lane] = xb;
    }
    __syncthreads();
    ha[tid] = va + (w ? wta[w - 1] : 0);
    hb[tid] = vb + (w ? wtb[w - 1] : 0);
    __syncthreads();
}

__global__ void __launch_bounds__(BT)
row_kernel(const float* __restrict__ up, const float* __restrict__ dn,
           const float* __restrict__ yt, const int* __restrict__ mk,
           float* __restrict__ out)
{
    __shared__ __align__(16) unsigned int s_oy[NVPAD * 4];   // 20.5 KB
    __shared__ __align__(16) float        s_up[NCOLS];       // 20 KB
    __shared__ int   s_hist[256];
    // s_bufU/s_bufD serve two temporally-disjoint roles (saves 2 KB -> 5 CTAs/SM):
    //   phase A (P2 + level-2 pick): int[256] histograms
    //   phase B (P3 + thresholds):   u64[CAP] candidate keys
    // The existing __syncthreads between the level-2 pick and P3 separates them.
    __shared__ __align__(16) unsigned long long s_bufU[CAP]; // 1 KB
    __shared__ __align__(16) unsigned long long s_bufD[CAP]; // 1 KB
    __shared__ int   s_cnt[2];
    __shared__ int   s_misc[8];   // 0:bU 1:rU 2:bD 3:rD 4:t16U 5:r2U 6:t16D 7:r2D
    __shared__ float s_scf[24];
    __shared__ int   s_sci[8];
    __shared__ int   s_wt[16];
    __shared__ unsigned long long s_thr[2];
    __shared__ unsigned int s_last;

    int* const s_histU = (int*)s_bufU;                  // 256 ints == 1 KB
    int* const s_histD = (int*)s_bufD;
    unsigned long long* const s_candU = s_bufU;         // CAP u64 == 1 KB
    unsigned long long* const s_candD = s_bufD;

    const int row = blockIdx.x, tid = threadIdx.x;
    const int lane = tid & 31, w = tid >> 5;
    const size_t base = (size_t)row * NCOLS;
    const float* dnr = dn + base;

    // zero histograms / counters
    s_hist[tid] = 0; s_histU[tid] = 0; s_histD[tid] = 0;
    if (tid < 2) s_cnt[tid] = 0;
    __syncthreads();

    // ---------- P1: vectorized load + stage + count/max + level-1 histogram ----
    const float4* y4 = (const float4*)(yt + base);
    const float4* u4 = (const float4*)(up + base);
    const int4*   m4 = (const int4*)(mk + base);

    int nv = 0; float m_y = -INFINITY, m_up = -INFINITY;

#define P1ELEM(YV, UV, MV, IDX) do {                                         \
        bool v_ = (MV) > 0;                                                  \
        unsigned int o_ = v_ ? ordf(YV) : 0u;                                \
        s_oy[IDX] = o_;                                                      \
        if (v_) { nv++; m_y = fmaxf(m_y, (YV)); m_up = fmaxf(m_up, (UV)); }  \
        unsigned int act_ = __ballot_sync(0xffffffffu, v_);                  \
        if (v_) {                                                            \
            unsigned int bin_ = o_ >> 24;                                    \
            unsigned int mm_ = __match_any_sync(act_, bin_);                 \
            if ((mm_ & ((1u << lane) - 1u)) == 0u)                           \
                atomicAdd(&s_hist[bin_], (int)__popc(mm_));                  \
        }                                                                    \
    } while (0)

#pragma unroll
    for (int i = tid; i < NVPAD; i += BT) {      // 5 uniform trips per thread
        bool inb = i < NVEC;
        float4 yv = make_float4(0.f, 0.f, 0.f, 0.f);
        float4 uv = yv;
        int4   mv = make_int4(0, 0, 0, 0);
        if (inb) {
            yv = y4[i]; uv = u4[i]; mv = m4[i];
            ((float4*)s_up)[i] = uv;
        }
        int idx = i * 4;
        P1ELEM(yv.x, uv.x, mv.x, idx + 0);
        P1ELEM(yv.y, uv.y, mv.y, idx + 1);
        P1ELEM(yv.z, uv.z, mv.z, idx + 2);
        P1ELEM(yv.w, uv.w, mv.w, idx + 3);
    }
    __syncthreads();

    blockReduceNMM(nv, m_y, m_up, s_sci, s_scf);

    float loss = 0.0f;
    if (nv > 0) {
        const int k = nv < TOPK ? nv : TOPK;

        // ---------- level-1 bin pick (both ends from one histogram) ----------
        scan256(s_hist, s_wt);
        {
            int pref = s_hist[tid];
            int cnt  = pref - (tid ? s_hist[tid - 1] : 0);
            if (cnt > 0) {
                int S = nv - pref;                     // strictly above this bin
                if (S < k && S + cnt >= k) { s_misc[0] = tid; s_misc[1] = k - S; }
                int below = pref - cnt;                // strictly below this bin
                if (below < k && pref >= k) { s_misc[2] = tid; s_misc[3] = k - below; }
            }
        }
        __syncthreads();
        const int bU = s_misc[0], rU = s_misc[1];
        const int bD = s_misc[2], rD = s_misc[3];

        // ---------- P2: sum-exp (+KL accumulator) + level-2 histograms -------
        float sul = 0.0f, syl = 0.0f, kac = 0.0f;
        for (int i = tid; i < NCOLS; i += BT) {
            unsigned int o = s_oy[i];
            if (!o) continue;
            float y = iordf(o);
            float u = s_up[i];
            float ey = __expf(y - m_y);
            float eu = __expf(u - m_up);
            syl += ey; sul += eu; kac += ey * (y - u);
            int b1 = (int)(o >> 24);
            if (b1 == bU) atomicAdd(&s_histU[(o >> 16) & 255u], 1);
            if (b1 == bD) atomicAdd(&s_histD[(o >> 16) & 255u], 1);
        }
        blockReduce3F(sul, syl, kac, s_scf);

        // ---------- level-2 bin pick ----------
        scan256dual(s_histU, s_histD, s_wt, s_wt + 8);
        {
            int prefU = s_histU[tid];
            int cntU  = prefU - (tid ? s_histU[tid - 1] : 0);
            int totU  = s_histU[255];
            if (cntU > 0) {
                int S = totU - prefU;
                if (S < rU && S + cntU >= rU) { s_misc[4] = (bU << 8) | tid; s_misc[5] = rU - S; }
            }
            int prefD = s_histD[tid];
            int cntD  = prefD - (tid ? s_histD[tid - 1] : 0);
            if (cntD > 0) {
                int below = prefD - cntD;
                if (below < rD && prefD >= rD) { s_misc[6] = (bD << 8) | tid; s_misc[7] = rD - below; }
            }
        }
        __syncthreads();                 // histograms dead past this point
        const unsigned int t16U = (unsigned int)s_misc[4];
        const unsigned int t16D = (unsigned int)s_misc[6];

        // ---------- P3: compact candidates in the two 16-bit bins ------------
        // (reuses s_bufU/s_bufD as u64 candidate arrays)
        for (int i = tid; i < NCOLS; i += BT) {
            unsigned int o = s_oy[i];
            if (!o) continue;
            unsigned int t = o >> 16;
            if (t == t16U) {
                int p = atomicAdd(&s_cnt[0], 1);
                if (p < CAP)
                    s_candU[p] = ((unsigned long long)o << 32) | (unsigned int)~i;
            }
            if (t == t16D) {
                int p = atomicAdd(&s_cnt[1], 1);
                if (p < CAP)
                    s_candD[p] = ((unsigned long long)(~o) << 32) | (unsigned int)~i;
            }
        }
        __syncthreads();

        // ---------- exact thresholds: warp0 -> up, warp1 -> down -------------
        if (w < 2) {
            int which = w;
            int cnt = s_cnt[which];
            int r   = s_misc[which ? 7 : 5];
            unsigned int t16 = which ? t16D : t16U;
            const unsigned long long* cand = which ? s_candD : s_candU;
            unsigned long long thr = ~0ull;
            if (cnt <= CAP) {
                for (int t = 0; t < r; t++) {
                    unsigned long long lm = 0ull;
                    for (int j = lane; j < cnt; j += 32) {
                        unsigned long long kk = cand[j];
                        if (kk < thr && kk > lm) lm = kk;
                    }
#pragma unroll
                    for (int o = 16; o; o >>= 1) {
                        unsigned long long v = __shfl_down_sync(0xffffffffu, lm, o);
                        if (v > lm) lm = v;
                    }
                    thr = __shfl_sync(0xffffffffu, lm, 0);
                }
            } else {   // overflow fallback: scan full array with bin filter
                for (int t = 0; t < r; t++) {
                    unsigned long long lm = 0ull;
                    for (int j = lane; j < NCOLS; j += 32) {
                        unsigned int o = s_oy[j];
                        if (!o || (o >> 16) != t16) continue;
                        unsigned long long kk = which
                            ? (((unsigned long long)(~o) << 32) | (unsigned int)~j)
                            : (((unsigned long long)o << 32) | (unsigned int)~j);
                        if (kk < thr && kk > lm) lm = kk;
                    }
#pragma unroll
                    for (int o = 16; o; o >>= 1) {
                        unsigned long long v = __shfl_down_sync(0xffffffffu, lm, o);
                        if (v > lm) lm = v;
                    }
                    thr = __shfl_sync(0xffffffffu, lm, 0);
                }
            }
            if (lane == 0) s_thr[which] = thr;
        }
        __syncthreads();
        const unsigned long long thrU = s_thr[0];
        const unsigned long long thrD = s_thr[1];

        // ---------- P4: BCE up/down ----------
        float bu = 0.0f, bd = 0.0f, dm = 0.0f;
        for (int i = tid; i < NCOLS; i += BT) {
            unsigned int o = s_oy[i];
            if (!o) continue;
            float u = s_up[i];
            float d = dnr[i];
            unsigned long long ku = ((unsigned long long)o << 32) | (unsigned int)~i;
            unsigned long long kd = ((unsigned long long)(~o) << 32) | (unsigned int)~i;
            float zu = (ku >= thrU) ? 1.0f : 0.0f;
            float zd = (kd >= thrD) ? 1.0f : 0.0f;

            // softplus(x) - x*z, stable form
            bu += fmaxf(u, 0.f) + __logf(1.f + __expf(-fabsf(u))) - u * zu;
            bd += fmaxf(d, 0.f) + __logf(1.f + __expf(-fabsf(d))) - d * zd;
        }
        blockReduce3F(bu, bd, dm, s_scf);

        // KL via algebraic fold: sum q(logq-logp) = kac/Sy + C
        float C  = (m_up + logf(sul)) - (m_y + logf(syl));
        float kl = kac / syl + C;
        loss = (bu + 0.5f * bd + 0.3f * kl) / (float)nv;
    }

    if (tid == 0) g_row[row] = loss;
    __threadfence();
    if (tid == 0) s_last = (atomicAdd(&g_ctr, 1u) == gridDim.x - 1u);
    __syncthreads();

    // last CTA reduces all rows (deterministic order) and writes scalar
    if (s_last) {
        __threadfence();
        float s = 0.f, d1 = 0.f, d2 = 0.f;
        for (int i = tid; i < (int)gridDim.x; i += BT) s += g_row[i];
        blockReduce3F(s, d1, d2, s_scf);
        if (tid == 0) { out[0] = s / (float)gridDim.x; g_ctr = 0u; }
    }
}

extern "C" void kernel_launch(void* const* d_in, const int* in_sizes, int n_in,
                              void* d_out, int out_size) {
    const float* up = (const float*)d_in[0];
    const float* dn = (const float*)d_in[1];
    const float* yt = (const float*)d_in[2];
    const int*   mk = (const int*)d_in[3];
    int B = in_sizes[0] / NCOLS;
    if (B > MAXB) B = MAXB;
    row_kernel<<<B, BT>>>(up, dn, yt, mk, (float*)d_out);
}

// round 17
// speedup vs baseline: 1.0058x; 1.0058x over previous
#include <cuda_runtime.h>
#include <cuda_bf16.h>
#include <math.h>

#define BT    256
#define NCOLS 5000
#define NVEC  1250      // NCOLS/4
#define NVPAD 1280      // ceil to multiple of BT (uniform warp trips for ballot)
#define TOPK  10
#define MAXB  8192
#define CAP   128

__device__ float        g_row[MAXB];
__device__ unsigned int g_ctr = 0;

// Order-preserving float<->uint bijection: f1<f2  <=>  ordf(f1)<ordf(f2)
__device__ __forceinline__ unsigned int ordf(float f) {
    unsigned int u = __float_as_uint(f);
    return (u & 0x80000000u) ? ~u : (u | 0x80000000u);
}
__device__ __forceinline__ float iordf(unsigned int o) {
    unsigned int u = (o & 0x80000000u) ? (o & 0x7fffffffu) : ~o;
    return __uint_as_float(u);
}

// Combined block reduce: sum(int), max(float), max(float)
__device__ __forceinline__ void blockReduceNMM(int& nv, float& my, float& mu,
                                               int* sci, float* scf) {
    int lane = threadIdx.x & 31, w = threadIdx.x >> 5;
    int n = nv; float a = my, b = mu;
#pragma unroll
    for (int o = 16; o; o >>= 1) {
        n += __shfl_down_sync(0xffffffffu, n, o);
        a = fmaxf(a, __shfl_down_sync(0xffffffffu, a, o));
        b = fmaxf(b, __shfl_down_sync(0xffffffffu, b, o));
    }
    if (lane == 0) { sci[w] = n; scf[w] = a; scf[8 + w] = b; }
    __syncthreads();
    if (w == 0) {
        int nn = lane < 8 ? sci[lane] : 0;
        float aa = lane < 8 ? scf[lane] : -INFINITY;
        float bb = lane < 8 ? scf[8 + lane] : -INFINITY;
#pragma unroll
        for (int o = 4; o; o >>= 1) {
            nn += __shfl_down_sync(0xffffffffu, nn, o);
            aa = fmaxf(aa, __shfl_down_sync(0xffffffffu, aa, o));
            bb = fmaxf(bb, __shfl_down_sync(0xffffffffu, bb, o));
        }
        if (lane == 0) { sci[0] = nn; scf[0] = aa; scf[8] = bb; }
    }
    __syncthreads();
    nv = sci[0]; my = scf[0]; mu = scf[8];
    __syncthreads();
}

// Combined block reduce: three float sums
__device__ __forceinline__ void blockReduce3F(float& a, float& b, float& c, float* scf) {
    int lane = threadIdx.x & 31, w = threadIdx.x >> 5;
#pragma unroll
    for (int o = 16; o; o >>= 1) {
        a += __shfl_down_sync(0xffffffffu, a, o);
        b += __shfl_down_sync(0xffffffffu, b, o);
        c += __shfl_down_sync(0xffffffffu, c, o);
    }
    if (lane == 0) { scf[w] = a; scf[8 + w] = b; scf[16 + w] = c; }
    __syncthreads();
    if (w == 0) {
        float x = lane < 8 ? scf[lane] : 0.0f;
        float y = lane < 8 ? scf[8 + lane] : 0.0f;
        float z = lane < 8 ? scf[16 + lane] : 0.0f;
#pragma unroll
        for (int o = 4; o; o >>= 1) {
            x += __shfl_down_sync(0xffffffffu, x, o);
            y += __shfl_down_sync(0xffffffffu, y, o);
            z += __shfl_down_sync(0xffffffffu, z, o);
        }
        if (lane == 0) { scf[0] = x; scf[8] = y; scf[16] = z; }
    }
    __syncthreads();
    a = scf[0]; b = scf[8]; c = scf[16];
    __syncthreads();
}

// In-place inclusive prefix scan of a 256-int shared array (BT==256 threads).
__device__ __forceinline__ void scan256(int* h, int* wtot) {
    int tid = threadIdx.x, lane = tid & 31, w = tid >> 5;
    int v = h[tid];
#pragma unroll
    for (int o = 1; o < 32; o <<= 1) {
        int t = __shfl_up_sync(0xffffffffu, v, o);
        if (lane >= o) v += t;
    }
    if (lane == 31) wtot[w] = v;
    __syncthreads();
    if (w == 0 && lane < 8) {
        int x = wtot[lane];
#pragma unroll
        for (int o = 1; o < 8; o <<= 1) {
            int t = __shfl_up_sync(0xffu, x, o);
            if (lane >= o) x += t;
        }
        wtot[lane] = x;
    }
    __syncthreads();
    h[tid] = v + (w ? wtot[w - 1] : 0);
    __syncthreads();
}

// Dual scan: two 256-int arrays at once (halves barrier count).
__device__ __forceinline__ void scan256dual(int* ha, int* hb, int* wta, int* wtb) {
    int tid = threadIdx.x, lane = tid & 31, w = tid >> 5;
    int va = ha[tid], vb = hb[tid];
#pragma unroll
    for (int o = 1; o < 32; o <<= 1) {
        int ta = __shfl_up_sync(0xffffffffu, va, o);
        int tb = __shfl_up_sync(0xffffffffu, vb, o);
        if (lane >= o) { va += ta; vb += tb; }
    }
    if (lane == 31) { wta[w] = va; wtb[w] = vb; }
    __syncthreads();
    if (w == 0 && lane < 8) {
        int xa = wta[lane], xb = wtb[lane];
#pragma unroll
        for (int o = 1; o < 8; o <<= 1) {
            int ta = __shfl_up_sync(0xffu, xa, o);
            int tb = __shfl_up_sync(0xffu, xb, o);
            if (lane >= o) { xa += ta; xb += tb; }
        }
        wta[lane] = xa; wtb[lane] = xb;
    }
    __syncthreads();
    ha[tid] = va + (w ? wta[w - 1] : 0);
    hb[tid] = vb + (w ? wtb[w - 1] : 0);
    __syncthreads();
}

__global__ void __launch_bounds__(BT)
row_kernel(const float* __restrict__ up, const float* __restrict__ dn,
           const float* __restrict__ yt, const int* __restrict__ mk,
           float* __restrict__ out)
{
    __shared__ __align__(16) unsigned int s_oy[NVPAD * 4];   // 20.5 KB
    __shared__ __align__(16) float        s_up[NCOLS];       // 20 KB
    __shared__ int   s_hist[256];
    // s_bufU/s_bufD serve two temporally-disjoint roles (saves 2 KB -> 5 CTAs/SM):
    //   phase A (P2 + level-2 pick): int[256] histograms
    //   phase B (P3 + thresholds):   u64[CAP] candidate keys
    __shared__ __align__(16) unsigned long long s_bufU[CAP]; // 1 KB
    __shared__ __align__(16) unsigned long long s_bufD[CAP]; // 1 KB
    __shared__ int   s_cnt[2];
    __shared__ int   s_misc[8];   // 0:bU 1:rU 2:bD 3:rD 4:t16U 5:r2U 6:t16D 7:r2D
    __shared__ float s_scf[24];
    __shared__ int   s_sci[8];
    __shared__ int   s_wt[16];
    __shared__ unsigned long long s_thr[2];
    __shared__ unsigned int s_last;

    int* const s_histU = (int*)s_bufU;                  // 256 ints == 1 KB
    int* const s_histD = (int*)s_bufD;
    unsigned long long* const s_candU = s_bufU;         // CAP u64 == 1 KB
    unsigned long long* const s_candD = s_bufD;

    const int row = blockIdx.x, tid = threadIdx.x;
    const int lane = tid & 31, w = tid >> 5;
    const size_t base = (size_t)row * NCOLS;
    const float* dnr = dn + base;

    // zero histograms / counters
    s_hist[tid] = 0; s_histU[tid] = 0; s_histD[tid] = 0;
    if (tid < 2) s_cnt[tid] = 0;
    __syncthreads();

    // ---------- P1: vectorized load + stage + count/max + level-1 histogram ----
    const float4* y4 = (const float4*)(yt + base);
    const float4* u4 = (const float4*)(up + base);
    const float4* d4 = (const float4*)(dnr);
    const int4*   m4 = (const int4*)(mk + base);

    int nv = 0; float m_y = -INFINITY, m_up = -INFINITY;

#define P1ELEM(YV, UV, MV, IDX) do {                                         \
        bool v_ = (MV) > 0;                                                  \
        unsigned int o_ = v_ ? ordf(YV) : 0u;                                \
        s_oy[IDX] = o_;                                                      \
        if (v_) { nv++; m_y = fmaxf(m_y, (YV)); m_up = fmaxf(m_up, (UV)); }  \
        unsigned int act_ = __ballot_sync(0xffffffffu, v_);                  \
        if (v_) {                                                            \
            unsigned int bin_ = o_ >> 24;                                    \
            unsigned int mm_ = __match_any_sync(act_, bin_);                 \
            if ((mm_ & ((1u << lane) - 1u)) == 0u)                           \
                atomicAdd(&s_hist[bin_], (int)__popc(mm_));                  \
        }                                                                    \
    } while (0)

#pragma unroll
    for (int i = tid; i < NVPAD; i += BT) {      // 5 uniform trips per thread
        bool inb = i < NVEC;
        float4 yv = make_float4(0.f, 0.f, 0.f, 0.f);
        float4 uv = yv;
        int4   mv = make_int4(0, 0, 0, 0);
        if (inb) {
            yv = y4[i]; uv = u4[i]; mv = m4[i];
            ((float4*)s_up)[i] = uv;
            // Warm L2 with this row's dn line: P4's scalar loads become L2 hits.
            asm volatile("prefetch.global.L2 [%0];" :: "l"(d4 + i));
        }
        int idx = i * 4;
        P1ELEM(yv.x, uv.x, mv.x, idx + 0);
        P1ELEM(yv.y, uv.y, mv.y, idx + 1);
        P1ELEM(yv.z, uv.z, mv.z, idx + 2);
        P1ELEM(yv.w, uv.w, mv.w, idx + 3);
    }
    __syncthreads();

    blockReduceNMM(nv, m_y, m_up, s_sci, s_scf);

    float loss = 0.0f;
    if (nv > 0) {
        const int k = nv < TOPK ? nv : TOPK;

        // ---------- level-1 bin pick (both ends from one histogram) ----------
        scan256(s_hist, s_wt);
        {
            int pref = s_hist[tid];
            int cnt  = pref - (tid ? s_hist[tid - 1] : 0);
            if (cnt > 0) {
                int S = nv - pref;                     // strictly above this bin
                if (S < k && S + cnt >= k) { s_misc[0] = tid; s_misc[1] = k - S; }
                int below = pref - cnt;                // strictly below this bin
                if (below < k && pref >= k) { s_misc[2] = tid; s_misc[3] = k - below; }
            }
        }
        __syncthreads();
        const int bU = s_misc[0], rU = s_misc[1];
        const int bD = s_misc[2], rD = s_misc[3];

        // ---------- P2: sum-exp (+KL accumulator) + level-2 histograms -------
        float sul = 0.0f, syl = 0.0f, kac = 0.0f;
        for (int i = tid; i < NCOLS; i += BT) {
            unsigned int o = s_oy[i];
            if (!o) continue;
            float y = iordf(o);
            float u = s_up[i];
            float ey = __expf(y - m_y);
            float eu = __expf(u - m_up);
            syl += ey; sul += eu; kac += ey * (y - u);
            int b1 = (int)(o >> 24);
            if (b1 == bU) atomicAdd(&s_histU[(o >> 16) & 255u], 1);
            if (b1 == bD) atomicAdd(&s_histD[(o >> 16) & 255u], 1);
        }
        blockReduce3F(sul, syl, kac, s_scf);

        // ---------- level-2 bin pick ----------
        scan256dual(s_histU, s_histD, s_wt, s_wt + 8);
        {
            int prefU = s_histU[tid];
            int cntU  = prefU - (tid ? s_histU[tid - 1] : 0);
            int totU  = s_histU[255];
            if (cntU > 0) {
                int S = totU - prefU;
                if (S < rU && S + cntU >= rU) { s_misc[4] = (bU << 8) | tid; s_misc[5] = rU - S; }
            }
            int prefD = s_histD[tid];
            int cntD  = prefD - (tid ? s_histD[tid - 1] : 0);
            if (cntD > 0) {
                int below = prefD - cntD;
                if (below < rD && prefD >= rD) { s_misc[6] = (bD << 8) | tid; s_misc[7] = rD - below; }
            }
        }
        __syncthreads();                 // histograms dead past this point
        const unsigned int t16U = (unsigned int)s_misc[4];
        const unsigned int t16D = (unsigned int)s_misc[6];

        // ---------- P3: compact candidates in the two 16-bit bins ------------
        // (reuses s_bufU/s_bufD as u64 candidate arrays)
        for (int i = tid; i < NCOLS; i += BT) {
            unsigned int o = s_oy[i];
            if (!o) continue;
            unsigned int t = o >> 16;
            if (t == t16U) {
                int p = atomicAdd(&s_cnt[0], 1);
                if (p < CAP)
                    s_candU[p] = ((unsigned long long)o << 32) | (unsigned int)~i;
            }
            if (t == t16D) {
                int p = atomicAdd(&s_cnt[1], 1);
                if (p < CAP)
                    s_candD[p] = ((unsigned long long)(~o) << 32) | (unsigned int)~i;
            }
        }
        __syncthreads();

        // ---------- exact thresholds: warp0 -> up, warp1 -> down -------------
        if (w < 2) {
            int which = w;
            int cnt = s_cnt[which];
            int r   = s_misc[which ? 7 : 5];
            unsigned int t16 = which ? t16D : t16U;
            const unsigned long long* cand = which ? s_candD : s_candU;
            unsigned long long thr = ~0ull;
            if (cnt <= CAP) {
                for (int t = 0; t < r; t++) {
                    unsigned long long lm = 0ull;
                    for (int j = lane; j < cnt; j += 32) {
                        unsigned long long kk = cand[j];
                        if (kk < thr && kk > lm) lm = kk;
                    }
#pragma unroll
                    for (int o = 16; o; o >>= 1) {
                        unsigned long long v = __shfl_down_sync(0xffffffffu, lm, o);
                        if (v > lm) lm = v;
                    }
                    thr = __shfl_sync(0xffffffffu, lm, 0);
                }
            } else {   // overflow fallback: scan full array with bin filter
                for (int t = 0; t < r; t++) {
                    unsigned long long lm = 0ull;
                    for (int j = lane; j < NCOLS; j += 32) {
                        unsigned int o = s_oy[j];
                        if (!o || (o >> 16) != t16) continue;
                        unsigned long long kk = which
                            ? (((unsigned long long)(~o) << 32) | (unsigned int)~j)
                            : (((unsigned long long)o << 32) | (unsigned int)~j);
                        if (kk < thr && kk > lm) lm = kk;
                    }
#pragma unroll
                    for (int o = 16; o; o >>= 1) {
                        unsigned long long v = __shfl_down_sync(0xffffffffu, lm, o);
                        if (v > lm) lm = v;
                    }
                    thr = __shfl_sync(0xffffffffu, lm, 0);
                }
            }
            if (lane == 0) s_thr[which] = thr;
        }
        __syncthreads();
        const unsigned long long thrU = s_thr[0];
        const unsigned long long thrD = s_thr[1];

        // ---------- P4: BCE up/down ----------
        float bu = 0.0f, bd = 0.0f, dm = 0.0f;
        for (int i = tid; i < NCOLS; i += BT) {
            unsigned int o = s_oy[i];
            if (!o) continue;
            float u = s_up[i];
            float d = dnr[i];
            unsigned long long ku = ((unsigned long long)o << 32) | (unsigned int)~i;
            unsigned long long kd = ((unsigned long long)(~o) << 32) | (unsigned int)~i;
            float zu = (ku >= thrU) ? 1.0f : 0.0f;
            float zd = (kd >= thrD) ? 1.0f : 0.0f;

            // softplus(x) - x*z, stable form
            bu += fmaxf(u, 0.f) + __logf(1.f + __expf(-fabsf(u))) - u * zu;
            bd += fmaxf(d, 0.f) + __logf(1.f + __expf(-fabsf(d))) - d * zd;
        }
        blockReduce3F(bu, bd, dm, s_scf);

        // KL via algebraic fold: sum q(logq-logp) = kac/Sy + C
        float C  = (m_up + logf(sul)) - (m_y + logf(syl));
        float kl = kac / syl + C;
        loss = (bu + 0.5f * bd + 0.3f * kl) / (float)nv;
    }

    if (tid == 0) g_row[row] = loss;
    __threadfence();
    if (tid == 0) s_last = (atomicAdd(&g_ctr, 1u) == gridDim.x - 1u);
    __syncthreads();

    // last CTA reduces all rows (deterministic order) and writes scalar
    if (s_last) {
        __threadfence();
        float s = 0.f, d1 = 0.f, d2 = 0.f;
        for (int i = tid; i < (int)gridDim.x; i += BT) s += g_row[i];
        blockReduce3F(s, d1, d2, s_scf);
        if (tid == 0) { out[0] = s / (float)gridDim.x; g_ctr = 0u; }
    }
}

extern "C" void kernel_launch(void* const* d_in, const int* in_sizes, int n_in,
                              void* d_out, int out_size) {
    const float* up = (const float*)d_in[0];
    const float* dn = (const float*)d_in[1];
    const float* yt = (const float*)d_in[2];
    const int*   mk = (const int*)d_in[3];
    int B = in_sizes[0] / NCOLS;
    if (B > MAXB) B = MAXB;
    row_kernel<<<B, BT>>>(up, dn, yt, mk, (float*)d_out);
}